// round 3
// baseline (speedup 1.0000x reference)
#include <cuda_runtime.h>

#define BB 256
#define NN 512
#define INF 10
#define HIDF 32
#define ROWS_PB 64
#define WARPS 8

// Scratch (allocation-free rule: __device__ globals)
__device__ float g_M[INF * INF];             // M = Q @ K^T  [10,10]
__device__ float g_t[BB * NN * INF];         // t = s @ M    [B,N,10]

// ---------------------------------------------------------------------------
// Kernel 0: M[a][b] = sum_m Qw[a][m] * Kw[b][m]   (Qw,Kw are [10,32] row-major)
// ---------------------------------------------------------------------------
__global__ void compute_M_kernel(const float* __restrict__ Qw,
                                 const float* __restrict__ Kw) {
    int idx = threadIdx.x;
    if (idx < INF * INF) {
        int a = idx / INF;
        int b = idx % INF;
        float sum = 0.0f;
#pragma unroll
        for (int m = 0; m < HIDF; m++)
            sum = fmaf(Qw[a * HIDF + m], Kw[b * HIDF + m], sum);
        g_M[idx] = sum;
    }
}

// ---------------------------------------------------------------------------
// Kernel 1: t[row][o] = sum_l s[row][l] * M[l][o]   (row = b*N+n)
// ---------------------------------------------------------------------------
__global__ void compute_t_kernel(const float* __restrict__ s) {
    __shared__ float Msh[INF * INF];
    if (threadIdx.x < INF * INF) Msh[threadIdx.x] = g_M[threadIdx.x];
    __syncthreads();

    int row = blockIdx.x * blockDim.x + threadIdx.x;
    if (row >= BB * NN) return;

    float sv[INF];
#pragma unroll
    for (int i = 0; i < INF; i++) sv[i] = s[(size_t)row * INF + i];

#pragma unroll
    for (int o = 0; o < INF; o++) {
        float acc = 0.0f;
#pragma unroll
        for (int l = 0; l < INF; l++) acc = fmaf(sv[l], Msh[l * INF + o], acc);
        g_t[(size_t)row * INF + o] = acc;
    }
}

// ---------------------------------------------------------------------------
// Kernel 2: fused scores^2 * Gmat + row-normalize.
// One block = one batch's chunk of ROWS_PB rows. One warp per row.
// s tile for the batch lives transposed in smem: s_sm[i][j], conflict-free.
// Lane handles j = lane + 32*u (u=0..15): coalesced Gmat loads + out stores.
// ---------------------------------------------------------------------------
__global__ __launch_bounds__(WARPS * 32) void attn_kernel(
    const float* __restrict__ s,
    const float* __restrict__ Gmat,
    float* __restrict__ out) {
    __shared__ float s_sm[INF][NN];
    __shared__ float t_sm[ROWS_PB][INF];

    const int chunks_per_batch = NN / ROWS_PB;
    const int b = blockIdx.x / chunks_per_batch;
    const int row0 = (blockIdx.x % chunks_per_batch) * ROWS_PB;

    // Load s[b] transposed into smem (one-time, 20 KB)
    const float* sb = s + (size_t)b * NN * INF;
    for (int idx = threadIdx.x; idx < NN * INF; idx += blockDim.x) {
        int n = idx / INF;
        int i = idx % INF;
        s_sm[i][n] = sb[idx];
    }
    // Load t chunk
    const float* tb = g_t + ((size_t)b * NN + row0) * INF;
    for (int idx = threadIdx.x; idx < ROWS_PB * INF; idx += blockDim.x)
        t_sm[idx / INF][idx % INF] = tb[idx];
    __syncthreads();

    const int warp = threadIdx.x >> 5;
    const int lane = threadIdx.x & 31;

    for (int r = warp; r < ROWS_PB; r += WARPS) {
        const int n = row0 + r;
        float tv[INF];
#pragma unroll
        for (int i = 0; i < INF; i++) tv[i] = t_sm[r][i];

        const float* gp = Gmat + ((size_t)b * NN + n) * NN;
        float* op = out + ((size_t)b * NN + n) * NN;

        float acc[16];
        float sum = 0.0f;
#pragma unroll
        for (int u = 0; u < 16; u++) {
            const int j = lane + (u << 5);
            float dot = 0.0f;
#pragma unroll
            for (int i = 0; i < INF; i++)
                dot = fmaf(tv[i], s_sm[i][j], dot);
            const float v = dot * dot * gp[j];
            acc[u] = v;
            sum += v;
        }

        // Warp-wide row sum
#pragma unroll
        for (int off = 16; off > 0; off >>= 1)
            sum += __shfl_xor_sync(0xffffffffu, sum, off);

        const float inv = 1.0f / (sum + 0.001f);
#pragma unroll
        for (int u = 0; u < 16; u++)
            op[lane + (u << 5)] = acc[u] * inv;
    }
}

// ---------------------------------------------------------------------------
extern "C" void kernel_launch(void* const* d_in, const int* in_sizes, int n_in,
                              void* d_out, int out_size) {
    const float* s    = (const float*)d_in[0];
    const float* Gmat = (const float*)d_in[1];
    const float* Qw   = (const float*)d_in[2];
    const float* Kw   = (const float*)d_in[3];
    float* out = (float*)d_out;

    compute_M_kernel<<<1, 128>>>(Qw, Kw);
    compute_t_kernel<<<(BB * NN + 255) / 256, 256>>>(s);
    attn_kernel<<<BB * (NN / ROWS_PB), WARPS * 32>>>(s, Gmat, out);
}

// round 4
// speedup vs baseline: 2.1203x; 2.1203x over previous
#include <cuda_runtime.h>

#define BB 256
#define NN 512
#define INF 10
#define HIDF 32
#define ROWS_PB 64
#define WARPS 8
#define THREADS (WARPS * 32)
#define CHUNKS (NN / ROWS_PB)

typedef unsigned long long u64;

// ---- packed f32x2 helpers (sm_103a FFMA2 path, PTX-only) -------------------
__device__ __forceinline__ u64 pk2(float lo, float hi) {
    u64 r; asm("mov.b64 %0,{%1,%2};" : "=l"(r) : "f"(lo), "f"(hi)); return r;
}
__device__ __forceinline__ void upk2(u64 v, float& lo, float& hi) {
    asm("mov.b64 {%0,%1},%2;" : "=f"(lo), "=f"(hi) : "l"(v));
}
__device__ __forceinline__ u64 fma2(u64 a, u64 b, u64 c) {
    u64 r; asm("fma.rn.f32x2 %0,%1,%2,%3;" : "=l"(r) : "l"(a), "l"(b), "l"(c)); return r;
}
__device__ __forceinline__ u64 mul2f(u64 a, u64 b) {
    u64 r; asm("mul.rn.f32x2 %0,%1,%2;" : "=l"(r) : "l"(a), "l"(b)); return r;
}
__device__ __forceinline__ u64 add2f(u64 a, u64 b) {
    u64 r; asm("add.rn.f32x2 %0,%1,%2;" : "=l"(r) : "l"(a), "l"(b)); return r;
}

// ---------------------------------------------------------------------------
// One fused kernel. Block = (batch b, 64-row chunk). Phases:
//   1. coop-load s[b] transposed into smem (conflict-free mapping) + M = Q K^T
//   2. t[r] = s[row] . M for the 64 chunk rows
//   3. main: warp handles 8 rows as 4 packed row-PAIRS; per j-column the
//      s_sm[i][j] loads are shared by both rows; dot/square/gmat/sum all in
//      packed f32x2; warp-reduce packed row sums; normalized stores.
// ---------------------------------------------------------------------------
__global__ __launch_bounds__(THREADS, 2) void attn_fused(
    const float* __restrict__ s,
    const float* __restrict__ Gmat,
    const float* __restrict__ Qw,
    const float* __restrict__ Kw,
    float* __restrict__ out) {
    __shared__ float s_sm[INF][NN];      // s[b] transposed: s_sm[i][n]
    __shared__ float M_sm[INF][INF];     // Q @ K^T
    __shared__ float t_sm[ROWS_PB][INF]; // t = s . M for this chunk

    const int tid = threadIdx.x;
    const int b = blockIdx.x / CHUNKS;
    const int row0 = (blockIdx.x % CHUNKS) * ROWS_PB;

    // ---- Phase 1a: s[b] -> smem transposed. Thread-per-n: STS conflict-free
    // (bank = n mod 32 for each fixed i), global reads L1/L2-absorbed.
    const float* sb = s + (size_t)b * NN * INF;
    for (int n = tid; n < NN; n += THREADS) {
#pragma unroll
        for (int i = 0; i < INF; i++)
            s_sm[i][n] = sb[n * INF + i];
    }
    // ---- Phase 1b: M[a][p] = sum_m Qw[a][m]*Kw[p][m]  (tiny, L2-hot reads)
    if (tid < INF * INF) {
        const int a = tid / INF, p = tid % INF;
        float acc = 0.0f;
#pragma unroll
        for (int m = 0; m < HIDF; m++)
            acc = fmaf(Qw[a * HIDF + m], Kw[p * HIDF + m], acc);
        M_sm[a][p] = acc;
    }
    __syncthreads();

    // ---- Phase 2: t_sm[r][o] = sum_l s_sm[l][row0+r] * M[l][o]
    if (tid < ROWS_PB) {
        const int n = row0 + tid;
        float sv[INF];
#pragma unroll
        for (int l = 0; l < INF; l++) sv[l] = s_sm[l][n];
#pragma unroll
        for (int o = 0; o < INF; o++) {
            float acc = 0.0f;
#pragma unroll
            for (int l = 0; l < INF; l++) acc = fmaf(sv[l], M_sm[l][o], acc);
            t_sm[tid][o] = acc;
        }
    }
    __syncthreads();

    // ---- Phase 3: main loop, 2 rows per pass packed in f32x2
    const int warp = tid >> 5;
    const int lane = tid & 31;

#pragma unroll
    for (int k = 0; k < 4; k++) {           // 4 row-pairs per warp
        const int r0 = (warp * 4 + k) * 2;  // rows r0, r0+1 of the chunk
        const int n0 = row0 + r0;

        u64 tp[INF];
#pragma unroll
        for (int i = 0; i < INF; i++)
            tp[i] = pk2(t_sm[r0][i], t_sm[r0 + 1][i]);

        const float* g0 = Gmat + ((size_t)b * NN + n0) * NN;
        const float* g1 = g0 + NN;
        float* o0 = out + ((size_t)b * NN + n0) * NN;
        float* o1 = o0 + NN;

        u64 acc[16];
        u64 sum2 = pk2(0.0f, 0.0f);
#pragma unroll
        for (int u = 0; u < 16; u++) {
            const int j = lane + (u << 5);
            u64 d = pk2(0.0f, 0.0f);
#pragma unroll
            for (int i = 0; i < INF; i++) {
                const float sj = s_sm[i][j];      // shared by both rows
                d = fma2(tp[i], pk2(sj, sj), d);
            }
            const u64 g = pk2(g0[j], g1[j]);
            const u64 v = mul2f(mul2f(d, d), g);  // scores^2 * Gmat, both rows
            acc[u] = v;
            sum2 = add2f(sum2, v);
        }

        // packed warp reduction of both row sums
#pragma unroll
        for (int off = 16; off > 0; off >>= 1)
            sum2 = add2f(sum2, __shfl_xor_sync(0xffffffffu, sum2, off));

        float sa, sb2;
        upk2(sum2, sa, sb2);
        const float inv0 = 1.0f / (sa + 0.001f);
        const float inv1 = 1.0f / (sb2 + 0.001f);

#pragma unroll
        for (int u = 0; u < 16; u++) {
            const int j = lane + (u << 5);
            float a, bv;
            upk2(acc[u], a, bv);
            o0[j] = a * inv0;
            o1[j] = bv * inv1;
        }
    }
}

// ---------------------------------------------------------------------------
extern "C" void kernel_launch(void* const* d_in, const int* in_sizes, int n_in,
                              void* d_out, int out_size) {
    const float* s    = (const float*)d_in[0];
    const float* Gmat = (const float*)d_in[1];
    const float* Qw   = (const float*)d_in[2];
    const float* Kw   = (const float*)d_in[3];
    float* out = (float*)d_out;

    attn_fused<<<BB * CHUNKS, THREADS>>>(s, Gmat, Qw, Kw, out);
}